// round 3
// baseline (speedup 1.0000x reference)
#include <cuda_runtime.h>
#include <math.h>

#define NB    8
#define HH    32
#define WW    32
#define CINC  256
#define CCONV 192
#define NHEAD 8
#define DKHD  8
#define DVHD  8
#define SEQ   1024

// ---------------- scratch (static device globals; no allocation) ----------------
__device__ float g_q[NB*NHEAD*SEQ*DKHD];   // [b][n][s][d], scaled by 8^-0.5
__device__ float g_k[NB*NHEAD*SEQ*DKHD];
__device__ float g_v[NB*NHEAD*SEQ*DVHD];
__device__ float g_attn[NB*SEQ*64];        // [b][s][n*8+d]

// ---------------- kernel 1: qkv projection + head split ----------------
// block = 32 positions x 192 outputs, 256 threads, 24 acc/thread
__global__ __launch_bounds__(256) void qkv_kernel(
    const float* __restrict__ x, const float* __restrict__ w,
    const float* __restrict__ bias)
{
    __shared__ float xs[32][32];
    __shared__ float ws[32][192];
    const int tid  = threadIdx.x;
    const int lane = tid & 31;
    const int wrp  = tid >> 5;
    const int p0   = blockIdx.x * 32;

    float acc[4][6];
    #pragma unroll
    for (int i = 0; i < 4; i++)
        #pragma unroll
        for (int j = 0; j < 6; j++) acc[i][j] = 0.f;

    for (int k0 = 0; k0 < CINC; k0 += 32) {
        __syncthreads();
        for (int i = tid; i < 32*32; i += 256) {
            int pp = i >> 5, c = i & 31;
            xs[pp][c] = x[(p0 + pp)*CINC + k0 + c];
        }
        for (int i = tid; i < 32*192; i += 256) {
            int c = i / 192, o = i % 192;
            ws[c][o] = w[(k0 + c)*192 + o];
        }
        __syncthreads();
        #pragma unroll
        for (int c = 0; c < 32; c++) {
            float a0 = xs[wrp     ][c];
            float a1 = xs[wrp +  8][c];
            float a2 = xs[wrp + 16][c];
            float a3 = xs[wrp + 24][c];
            float b[6];
            #pragma unroll
            for (int j = 0; j < 6; j++) b[j] = ws[c][lane + 32*j];
            #pragma unroll
            for (int j = 0; j < 6; j++) {
                acc[0][j] = fmaf(a0, b[j], acc[0][j]);
                acc[1][j] = fmaf(a1, b[j], acc[1][j]);
                acc[2][j] = fmaf(a2, b[j], acc[2][j]);
                acc[3][j] = fmaf(a3, b[j], acc[3][j]);
            }
        }
    }
    #pragma unroll
    for (int i = 0; i < 4; i++) {
        int p = p0 + wrp + 8*i;
        int b = p >> 10, s = p & 1023;
        #pragma unroll
        for (int j = 0; j < 6; j++) {
            int o = lane + 32*j;
            float v = acc[i][j] + bias[o];
            if (o < 64) {
                g_k[((b*8 + (o >> 3))*SEQ + s)*8 + (o & 7)] = v;
            } else if (o < 128) {
                int oq = o - 64;
                g_q[((b*8 + (oq >> 3))*SEQ + s)*8 + (oq & 7)] = v * 0.35355339059327373f;
            } else {
                int ov = o - 128;
                g_v[((b*8 + (ov >> 3))*SEQ + s)*8 + (ov & 7)] = v;
            }
        }
    }
}

// ---------------- kernel 2: 3x3 SAME conv, 256 -> 192 channels ----------------
// block = one image row (b,y): 32 positions x 192 channels, 256 threads
__global__ __launch_bounds__(256) void conv_kernel(
    const float* __restrict__ x, const float* __restrict__ w,
    const float* __restrict__ bias, float* __restrict__ out)
{
    __shared__ float xs[34][32];
    __shared__ float ws[32][192];
    const int tid  = threadIdx.x;
    const int lane = tid & 31;
    const int wrp  = tid >> 5;
    const int blk  = blockIdx.x;          // b*32 + y
    const int b    = blk >> 5;
    const int y    = blk & 31;

    float acc[4][6];
    #pragma unroll
    for (int i = 0; i < 4; i++)
        #pragma unroll
        for (int j = 0; j < 6; j++) acc[i][j] = 0.f;

    for (int ky = 0; ky < 3; ky++) {
        int yy = y + ky - 1;
        if (yy < 0 || yy >= HH) continue;
        const float* xrow = x + (b*SEQ + yy*WW)*CINC;
        for (int k0 = 0; k0 < CINC; k0 += 32) {
            __syncthreads();
            for (int i = tid; i < 34*32; i += 256) {
                int xc = i >> 5, c = i & 31;
                int xg = xc - 1;
                xs[xc][c] = (xg >= 0 && xg < WW) ? xrow[xg*CINC + k0 + c] : 0.f;
            }
            for (int kx = 0; kx < 3; kx++) {
                __syncthreads();
                for (int i = tid; i < 32*192; i += 256) {
                    int c = i / 192, o = i % 192;
                    ws[c][o] = w[((ky*3 + kx)*CINC + (k0 + c))*192 + o];
                }
                __syncthreads();
                #pragma unroll
                for (int c = 0; c < 32; c++) {
                    float a0 = xs[wrp      + kx][c];
                    float a1 = xs[wrp +  8 + kx][c];
                    float a2 = xs[wrp + 16 + kx][c];
                    float a3 = xs[wrp + 24 + kx][c];
                    float bb[6];
                    #pragma unroll
                    for (int j = 0; j < 6; j++) bb[j] = ws[c][lane + 32*j];
                    #pragma unroll
                    for (int j = 0; j < 6; j++) {
                        acc[0][j] = fmaf(a0, bb[j], acc[0][j]);
                        acc[1][j] = fmaf(a1, bb[j], acc[1][j]);
                        acc[2][j] = fmaf(a2, bb[j], acc[2][j]);
                        acc[3][j] = fmaf(a3, bb[j], acc[3][j]);
                    }
                }
            }
        }
    }
    #pragma unroll
    for (int i = 0; i < 4; i++) {
        int p = b*SEQ + y*WW + (wrp + 8*i);
        #pragma unroll
        for (int j = 0; j < 6; j++) {
            int o = lane + 32*j;
            out[p*256 + o] = acc[i][j] + bias[o];
        }
    }
}

// ---------------- kernel 3: fused attention (per b, head, query-row) ----------------
// logits[i,j] = q_i.k_j + q_i.relw[yj-yi+31] + q_i.relh[xj-xi+31]
// block = (b, n, xi): 32 queries x 1024 keys. warp w owns queries yq in [4w,4w+4),
// lane l owns keys j = t*32 + l  (=> y_j = l, x_j = t). Two-pass softmax.
__global__ __launch_bounds__(256, 2) void attn_kernel(
    const float* __restrict__ rel_w, const float* __restrict__ rel_h)
{
    extern __shared__ float sm[];
    float* Ks = sm;                 // 1024*9
    float* Vs = sm + 9216;          // 1024*9
    float* rw = sm + 18432;         // [yq][yj] 32*32
    float* rh = sm + 19456;         // [yq][xj] 32*32
    float* qs = sm + 20480;         // [yq][d] 32*8 (reused as output staging)

    const int tid  = threadIdx.x;
    const int lane = tid & 31;
    const int wrp  = tid >> 5;
    const int blk  = blockIdx.x;    // bn*32 + xi
    const int bn   = blk >> 5;
    const int xi   = blk & 31;

    const float* kg = g_k + bn*SEQ*8;
    const float* vg = g_v + bn*SEQ*8;
    const float* qg = g_q + bn*SEQ*8 + xi*32*8;

    for (int i = tid; i < SEQ*8; i += 256) {
        int j = i >> 3, d = i & 7;
        Ks[j*9 + d] = kg[i];
        Vs[j*9 + d] = vg[i];
    }
    qs[tid] = qg[tid];    // 256 floats
    __syncthreads();

    for (int e = tid; e < 1024; e += 256) {
        int yq = e >> 5, yj = e & 31;
        const float* rk = rel_w + (yj - yq + 31)*8;
        float s = 0.f;
        #pragma unroll
        for (int d = 0; d < 8; d++) s = fmaf(qs[yq*8 + d], rk[d], s);
        rw[e] = s;
    }
    for (int e = tid; e < 1024; e += 256) {
        int yq = e >> 5, xj = e & 31;
        const float* rk = rel_h + (xj - xi + 31)*8;
        float s = 0.f;
        #pragma unroll
        for (int d = 0; d < 8; d++) s = fmaf(qs[yq*8 + d], rk[d], s);
        rh[e] = s;
    }
    __syncthreads();

    const int w4 = wrp * 4;
    float qv[4][8];
    float rwd[4];
    #pragma unroll
    for (int qi = 0; qi < 4; qi++) {
        rwd[qi] = rw[(w4 + qi)*32 + lane];
        #pragma unroll
        for (int d = 0; d < 8; d++) qv[qi][d] = qs[(w4 + qi)*8 + d];
    }

    // pass 1: row max
    float mx[4] = {-1e30f, -1e30f, -1e30f, -1e30f};
    for (int t = 0; t < 32; t++) {
        const float* kk = &Ks[(t*32 + lane)*9];
        float kv[8];
        #pragma unroll
        for (int d = 0; d < 8; d++) kv[d] = kk[d];
        #pragma unroll
        for (int qi = 0; qi < 4; qi++) {
            float lg = rwd[qi] + rh[(w4 + qi)*32 + t];
            #pragma unroll
            for (int d = 0; d < 8; d++) lg = fmaf(qv[qi][d], kv[d], lg);
            mx[qi] = fmaxf(mx[qi], lg);
        }
    }
    #pragma unroll
    for (int off = 16; off > 0; off >>= 1)
        #pragma unroll
        for (int qi = 0; qi < 4; qi++)
            mx[qi] = fmaxf(mx[qi], __shfl_xor_sync(0xffffffffu, mx[qi], off));

    // pass 2: exp + accumulate
    float ssum[4] = {0.f, 0.f, 0.f, 0.f};
    float acc[4][8];
    #pragma unroll
    for (int qi = 0; qi < 4; qi++)
        #pragma unroll
        for (int d = 0; d < 8; d++) acc[qi][d] = 0.f;

    for (int t = 0; t < 32; t++) {
        const float* kk = &Ks[(t*32 + lane)*9];
        const float* vv0 = &Vs[(t*32 + lane)*9];
        float kv[8], vv[8];
        #pragma unroll
        for (int d = 0; d < 8; d++) { kv[d] = kk[d]; vv[d] = vv0[d]; }
        #pragma unroll
        for (int qi = 0; qi < 4; qi++) {
            float lg = rwd[qi] + rh[(w4 + qi)*32 + t];
            #pragma unroll
            for (int d = 0; d < 8; d++) lg = fmaf(qv[qi][d], kv[d], lg);
            float p = __expf(lg - mx[qi]);
            ssum[qi] += p;
            #pragma unroll
            for (int d = 0; d < 8; d++) acc[qi][d] = fmaf(p, vv[d], acc[qi][d]);
        }
    }
    #pragma unroll
    for (int off = 16; off > 0; off >>= 1) {
        #pragma unroll
        for (int qi = 0; qi < 4; qi++) {
            ssum[qi] += __shfl_xor_sync(0xffffffffu, ssum[qi], off);
            #pragma unroll
            for (int d = 0; d < 8; d++)
                acc[qi][d] += __shfl_xor_sync(0xffffffffu, acc[qi][d], off);
        }
    }
    __syncthreads();   // qs reads done everywhere; safe to reuse as staging
    if (lane == 0) {
        #pragma unroll
        for (int qi = 0; qi < 4; qi++) {
            float inv = 1.f / ssum[qi];
            #pragma unroll
            for (int d = 0; d < 8; d++) qs[(w4 + qi)*8 + d] = acc[qi][d] * inv;
        }
    }
    __syncthreads();
    {
        int b = bn >> 3, n = bn & 7;
        int yq = tid >> 3, d = tid & 7;
        g_attn[(b*SEQ + xi*32 + yq)*64 + n*8 + d] = qs[tid];
    }
}

// ---------------- kernel 4: 64x64 output projection into channels [192,256) ----------------
__global__ __launch_bounds__(256) void proj_kernel(
    const float* __restrict__ w, const float* __restrict__ bias,
    float* __restrict__ out)
{
    __shared__ float at[32][64];
    __shared__ float ws[64][64];
    const int tid = threadIdx.x;
    const int p0  = blockIdx.x * 32;

    for (int i = tid; i < 32*64; i += 256) at[i >> 6][i & 63] = g_attn[p0*64 + i];
    for (int i = tid; i < 64*64; i += 256) ws[i >> 6][i & 63] = w[i];
    __syncthreads();

    const int o  = tid & 63;
    const int pg = tid >> 6;        // 0..3
    float acc[8];
    #pragma unroll
    for (int i = 0; i < 8; i++) acc[i] = 0.f;

    #pragma unroll
    for (int c = 0; c < 64; c++) {
        float wv = ws[c][o];
        #pragma unroll
        for (int i = 0; i < 8; i++)
            acc[i] = fmaf(at[pg + 4*i][c], wv, acc[i]);
    }
    float bb = bias[o];
    #pragma unroll
    for (int i = 0; i < 8; i++)
        out[(p0 + pg + 4*i)*256 + 192 + o] = acc[i] + bb;
}

// ---------------- launch ----------------
extern "C" void kernel_launch(void* const* d_in, const int* in_sizes, int n_in,
                              void* d_out, int out_size)
{
    const float* x       = (const float*)d_in[0];
    const float* conv_w  = (const float*)d_in[1];
    const float* conv_b  = (const float*)d_in[2];
    const float* qkv_w   = (const float*)d_in[3];
    const float* qkv_b   = (const float*)d_in[4];
    const float* attn_w  = (const float*)d_in[5];
    const float* attn_b  = (const float*)d_in[6];
    const float* relw    = (const float*)d_in[7];
    const float* relh    = (const float*)d_in[8];
    float* out = (float*)d_out;

    const int ATTN_SMEM = 20736 * 4;   // 82944 B dynamic
    cudaFuncSetAttribute(attn_kernel, cudaFuncAttributeMaxDynamicSharedMemorySize, ATTN_SMEM);

    qkv_kernel<<<NB*SEQ/32, 256>>>(x, qkv_w, qkv_b);
    conv_kernel<<<NB*HH, 256>>>(x, conv_w, conv_b, out);
    attn_kernel<<<NB*NHEAD*HH, 256, ATTN_SMEM>>>(relw, relh);
    proj_kernel<<<NB*SEQ/32, 256>>>(attn_w, attn_b, out);
}

// round 5
// speedup vs baseline: 1.8291x; 1.8291x over previous
#include <cuda_runtime.h>
#include <cuda_bf16.h>
#include <math.h>
#include <stdint.h>

#define NB    8
#define HH    32
#define WW    32
#define CINC  256
#define NHEAD 8
#define SEQ   1024

// ---------------- scratch (static device globals; no allocation) ----------------
__device__ float g_q[NB*NHEAD*SEQ*8];
__device__ float g_k[NB*NHEAD*SEQ*8];
__device__ float g_v[NB*NHEAD*SEQ*8];
__device__ float g_attn[NB*SEQ*64];

// split-bf16 transposed weights: conv B (192 x 2304), qkv B (192 x 256)
__device__ __align__(16) __nv_bfloat16 g_Bhi[192*2304];
__device__ __align__(16) __nv_bfloat16 g_Blo[192*2304];
__device__ __align__(16) __nv_bfloat16 g_QBhi[192*256];
__device__ __align__(16) __nv_bfloat16 g_QBlo[192*256];

// ================= warp-level bf16 MMA (sm_80+ PTX; works on plain compute_103) ====
__device__ __forceinline__ void mma_bf16(float* c, const uint32_t* a, const uint32_t* b)
{
    asm volatile(
        "mma.sync.aligned.m16n8k16.row.col.f32.bf16.bf16.f32 "
        "{%0,%1,%2,%3}, {%4,%5,%6,%7}, {%8,%9}, {%0,%1,%2,%3};\n"
        : "+f"(c[0]), "+f"(c[1]), "+f"(c[2]), "+f"(c[3])
        : "r"(a[0]), "r"(a[1]), "r"(a[2]), "r"(a[3]),
          "r"(b[0]), "r"(b[1]));
}

// ================= weight prep: transpose + hi/lo split =================
__global__ __launch_bounds__(256) void bprep_kernel(
    const float* __restrict__ conv_w, const float* __restrict__ qkv_w)
{
    int idx = blockIdx.x * 256 + threadIdx.x;
    if (idx < 192*2304) {
        int n = idx / 2304, k = idx - n*2304;
        float v = conv_w[k*192 + n];
        __nv_bfloat16 h = __float2bfloat16(v);
        g_Bhi[idx] = h;
        g_Blo[idx] = __float2bfloat16(v - __bfloat162float(h));
    } else {
        int j = idx - 192*2304;
        if (j < 192*256) {
            int n = j / 256, k = j - n*256;
            float v = qkv_w[k*192 + n];
            __nv_bfloat16 h = __float2bfloat16(v);
            g_QBhi[j] = h;
            g_QBlo[j] = __float2bfloat16(v - __bfloat162float(h));
        }
    }
}

// ================= qkv scatter helper =================
__device__ __forceinline__ void qkv_store(int row, int col, float v, const float* bias)
{
    v += bias[col];
    int b = row >> 10, s = row & 1023;
    if (col < 64) {
        g_k[((b*8 + (col >> 3))*SEQ + s)*8 + (col & 7)] = v;
    } else if (col < 128) {
        int o = col - 64;
        g_q[((b*8 + (o >> 3))*SEQ + s)*8 + (o & 7)] = v * 0.35355339059327373f;
    } else {
        int o = col - 128;
        g_v[((b*8 + (o >> 3))*SEQ + s)*8 + (o & 7)] = v;
    }
}

// ================= unified split-bf16 GEMM (MODE 0 = conv-im2col, MODE 1 = qkv) =====
// M = 8192 (BM=64, 128 CTAs), N = 192 (3 warp cols x 48), BK = 32.
// A: fp32 from x, converted to hi/lo bf16 in-register (implicit im2col for MODE 0).
// B: pre-split bf16 weights. 3 MMA passes: Ahi*Bhi + Ahi*Blo + Alo*Bhi, fp32 accum.
// smem stage (bf16 elems): AHI[64*40]=2560, ALO=2560, BHI[192*40]=7680, BLO=7680 -> 20480
#define STG_ELEMS 20480
#define GEMM_SMEM (2*STG_ELEMS*2)

template<int MODE>
__global__ __launch_bounds__(256, 1) void gemm_kernel(
    const float* __restrict__ x,
    const __nv_bfloat16* __restrict__ Bhi,
    const __nv_bfloat16* __restrict__ Blo,
    const float* __restrict__ bias,
    float* __restrict__ out)
{
    constexpr int NC = MODE ? 8 : 72;
    constexpr int KB = MODE ? 256 : 2304;

    extern __shared__ __align__(16) __nv_bfloat16 sm[];

    const int tid  = threadIdx.x;
    const int lane = tid & 31;
    const int wid  = tid >> 5;
    const int mt   = blockIdx.x;

    // ---- A loader coords: thread -> (row, 8-channel group) ----
    const int ar  = tid >> 2;           // 0..63 (position row in tile)
    const int acg = (tid & 3) * 8;      // channel offset within 32-chunk
    const int p   = mt*64 + ar;
    const int pb  = p >> 10, py = (p >> 5) & 31, px = p & 31;

    float aregs[8];
    uint4 bregs[6];

    // ---- warp tile coords ----
    const int wm = (wid >> 2) * 32;     // 0 / 32
    const int wn = (wid & 3) * 48;      // 0 / 48 / 96 / 144
    const int g  = lane >> 2;
    const int tg = lane & 3;

    float acc[2][6][4];
    #pragma unroll
    for (int mi = 0; mi < 2; mi++)
        #pragma unroll
        for (int ni = 0; ni < 6; ni++)
            #pragma unroll
            for (int e = 0; e < 4; e++) acc[mi][ni][e] = 0.f;

    auto ldgA = [&](int kc) {
        int dy, dx, c0;
        if (MODE) { dy = 0; dx = 0; c0 = kc * 32; }
        else { int t = kc >> 3; dy = t/3 - 1; dx = t%3 - 1; c0 = (kc & 7) * 32; }
        int yy = py + dy, xx = px + dx;
        bool valid = MODE ? true : ((unsigned)yy < 32u && (unsigned)xx < 32u);
        if (valid) {
            const float4* s = reinterpret_cast<const float4*>(
                x + ((size_t)(pb*1024 + yy*32 + xx))*256 + c0 + acg);
            float4 v0 = s[0], v1 = s[1];
            aregs[0]=v0.x; aregs[1]=v0.y; aregs[2]=v0.z; aregs[3]=v0.w;
            aregs[4]=v1.x; aregs[5]=v1.y; aregs[6]=v1.z; aregs[7]=v1.w;
        } else {
            #pragma unroll
            for (int i = 0; i < 8; i++) aregs[i] = 0.f;
        }
    };

    auto ldgB = [&](int kc) {
        const int kbase = kc * 32;
        #pragma unroll
        for (int i = 0; i < 6; i++) {
            int idx  = tid + i*256;          // 0..1535
            int half = idx >= 768;
            int j    = idx - half*768;
            int n    = j >> 2, gg = (j & 3) * 8;
            const __nv_bfloat16* src = (half ? Blo : Bhi) + (size_t)n*KB + kbase + gg;
            bregs[i] = *reinterpret_cast<const uint4*>(src);
        }
    };

    auto stsA = [&](int st) {
        __nv_bfloat16* As = sm + st*STG_ELEMS;
        __nv_bfloat162 h[4], l[4];
        #pragma unroll
        for (int i = 0; i < 4; i++) {
            float v0 = aregs[2*i], v1 = aregs[2*i+1];
            __nv_bfloat16 h0 = __float2bfloat16(v0), h1 = __float2bfloat16(v1);
            h[i].x = h0; h[i].y = h1;
            l[i].x = __float2bfloat16(v0 - __bfloat162float(h0));
            l[i].y = __float2bfloat16(v1 - __bfloat162float(h1));
        }
        *reinterpret_cast<uint4*>(As + ar*40 + acg)        = *reinterpret_cast<uint4*>(h);
        *reinterpret_cast<uint4*>(As + 2560 + ar*40 + acg) = *reinterpret_cast<uint4*>(l);
    };

    auto stsB = [&](int st) {
        __nv_bfloat16* Bs = sm + st*STG_ELEMS + 5120;
        #pragma unroll
        for (int i = 0; i < 6; i++) {
            int idx  = tid + i*256;
            int half = idx >= 768;
            int j    = idx - half*768;
            int n    = j >> 2, gg = (j & 3) * 8;
            *reinterpret_cast<uint4*>(Bs + half*7680 + n*40 + gg) = bregs[i];
        }
    };

    auto compute = [&](int st) {
        const uint32_t* As = reinterpret_cast<const uint32_t*>(sm + st*STG_ELEMS);
        const uint32_t* Bs = reinterpret_cast<const uint32_t*>(sm + st*STG_ELEMS + 5120);
        #pragma unroll
        for (int ks = 0; ks < 2; ks++) {
            const int k0 = ks * 8;                       // b32 units (16 bf16)
            uint32_t ahi[2][4], alo[2][4];
            #pragma unroll
            for (int mi = 0; mi < 2; mi++) {
                int base = (wm + mi*16 + g)*20 + k0 + tg;
                ahi[mi][0] = As[base];        ahi[mi][1] = As[base + 160];
                ahi[mi][2] = As[base + 4];    ahi[mi][3] = As[base + 164];
                alo[mi][0] = As[1280 + base];       alo[mi][1] = As[1280 + base + 160];
                alo[mi][2] = As[1280 + base + 4];   alo[mi][3] = As[1280 + base + 164];
            }
            uint32_t bhi[6][2], blo[6][2];
            #pragma unroll
            for (int ni = 0; ni < 6; ni++) {
                int base = (wn + ni*8 + g)*20 + k0 + tg;
                bhi[ni][0] = Bs[base];        bhi[ni][1] = Bs[base + 4];
                blo[ni][0] = Bs[3840 + base]; blo[ni][1] = Bs[3840 + base + 4];
            }
            #pragma unroll
            for (int mi = 0; mi < 2; mi++)
                #pragma unroll
                for (int ni = 0; ni < 6; ni++) {
                    mma_bf16(acc[mi][ni], ahi[mi], bhi[ni]);
                    mma_bf16(acc[mi][ni], ahi[mi], blo[ni]);
                    mma_bf16(acc[mi][ni], alo[mi], bhi[ni]);
                }
        }
    };

    // ---- 2-stage pipeline with register prefetch ----
    ldgA(0); ldgB(0); stsA(0); stsB(0);
    for (int kc = 0; kc < NC; kc++) {
        if (kc + 1 < NC) { ldgA(kc+1); ldgB(kc+1); }
        __syncthreads();
        compute(kc & 1);
        if (kc + 1 < NC) { stsA((kc+1) & 1); stsB((kc+1) & 1); }
    }

    // ---- epilogue ----
    if (MODE == 0) {
        #pragma unroll
        for (int mi = 0; mi < 2; mi++)
            #pragma unroll
            for (int ni = 0; ni < 6; ni++) {
                int col  = wn + ni*8 + tg*2;
                int row0 = mt*64 + wm + mi*16 + g;
                float b0 = bias[col], b1 = bias[col+1];
                float2 v0 = make_float2(acc[mi][ni][0] + b0, acc[mi][ni][1] + b1);
                float2 v1 = make_float2(acc[mi][ni][2] + b0, acc[mi][ni][3] + b1);
                *reinterpret_cast<float2*>(out + (size_t)row0*256 + col)     = v0;
                *reinterpret_cast<float2*>(out + (size_t)(row0+8)*256 + col) = v1;
            }
    } else {
        #pragma unroll
        for (int mi = 0; mi < 2; mi++)
            #pragma unroll
            for (int ni = 0; ni < 6; ni++) {
                int col = wn + ni*8 + tg*2;
                int row = mt*64 + wm + mi*16 + g;
                qkv_store(row,     col,     acc[mi][ni][0], bias);
                qkv_store(row,     col + 1, acc[mi][ni][1], bias);
                qkv_store(row + 8, col,     acc[mi][ni][2], bias);
                qkv_store(row + 8, col + 1, acc[mi][ni][3], bias);
            }
    }
}

// ================= fused attention (unchanged) =================
__global__ __launch_bounds__(256, 2) void attn_kernel(
    const float* __restrict__ rel_w, const float* __restrict__ rel_h)
{
    extern __shared__ float smf[];
    float* Ks = smf;
    float* Vs = smf + 9216;
    float* rw = smf + 18432;
    float* rh = smf + 19456;
    float* qs = smf + 20480;

    const int tid  = threadIdx.x;
    const int lane = tid & 31;
    const int wrp  = tid >> 5;
    const int blk  = blockIdx.x;
    const int bn   = blk >> 5;
    const int xi   = blk & 31;

    const float* kg = g_k + bn*SEQ*8;
    const float* vg = g_v + bn*SEQ*8;
    const float* qg = g_q + bn*SEQ*8 + xi*32*8;

    for (int i = tid; i < SEQ*8; i += 256) {
        int j = i >> 3, d = i & 7;
        Ks[j*9 + d] = kg[i];
        Vs[j*9 + d] = vg[i];
    }
    qs[tid] = qg[tid];
    __syncthreads();

    for (int e = tid; e < 1024; e += 256) {
        int yq = e >> 5, yj = e & 31;
        const float* rk = rel_w + (yj - yq + 31)*8;
        float s = 0.f;
        #pragma unroll
        for (int d = 0; d < 8; d++) s = fmaf(qs[yq*8 + d], rk[d], s);
        rw[e] = s;
    }
    for (int e = tid; e < 1024; e += 256) {
        int yq = e >> 5, xj = e & 31;
        const float* rk = rel_h + (xj - xi + 31)*8;
        float s = 0.f;
        #pragma unroll
        for (int d = 0; d < 8; d++) s = fmaf(qs[yq*8 + d], rk[d], s);
        rh[e] = s;
    }
    __syncthreads();

    const int w4 = wrp * 4;
    float qv[4][8];
    float rwd[4];
    #pragma unroll
    for (int qi = 0; qi < 4; qi++) {
        rwd[qi] = rw[(w4 + qi)*32 + lane];
        #pragma unroll
        for (int d = 0; d < 8; d++) qv[qi][d] = qs[(w4 + qi)*8 + d];
    }

    float mx[4] = {-1e30f, -1e30f, -1e30f, -1e30f};
    for (int t = 0; t < 32; t++) {
        const float* kk = &Ks[(t*32 + lane)*9];
        float kv[8];
        #pragma unroll
        for (int d = 0; d < 8; d++) kv[d] = kk[d];
        #pragma unroll
        for (int qi = 0; qi < 4; qi++) {
            float lg = rwd[qi] + rh[(w4 + qi)*32 + t];
            #pragma unroll
            for (int d = 0; d < 8; d++) lg = fmaf(qv[qi][d], kv[d], lg);
            mx[qi] = fmaxf(mx[qi], lg);
        }
    }
    #pragma unroll
    for (int off = 16; off > 0; off >>= 1)
        #pragma unroll
        for (int qi = 0; qi < 4; qi++)
            mx[qi] = fmaxf(mx[qi], __shfl_xor_sync(0xffffffffu, mx[qi], off));

    float ssum[4] = {0.f, 0.f, 0.f, 0.f};
    float acc[4][8];
    #pragma unroll
    for (int qi = 0; qi < 4; qi++)
        #pragma unroll
        for (int d = 0; d < 8; d++) acc[qi][d] = 0.f;

    for (int t = 0; t < 32; t++) {
        const float* kk  = &Ks[(t*32 + lane)*9];
        const float* vv0 = &Vs[(t*32 + lane)*9];
        float kv[8], vv[8];
        #pragma unroll
        for (int d = 0; d < 8; d++) { kv[d] = kk[d]; vv[d] = vv0[d]; }
        #pragma unroll
        for (int qi = 0; qi < 4; qi++) {
            float lg = rwd[qi] + rh[(w4 + qi)*32 + t];
            #pragma unroll
            for (int d = 0; d < 8; d++) lg = fmaf(qv[qi][d], kv[d], lg);
            float pp = __expf(lg - mx[qi]);
            ssum[qi] += pp;
            #pragma unroll
            for (int d = 0; d < 8; d++) acc[qi][d] = fmaf(pp, vv[d], acc[qi][d]);
        }
    }
    #pragma unroll
    for (int off = 16; off > 0; off >>= 1) {
        #pragma unroll
        for (int qi = 0; qi < 4; qi++) {
            ssum[qi] += __shfl_xor_sync(0xffffffffu, ssum[qi], off);
            #pragma unroll
            for (int d = 0; d < 8; d++)
                acc[qi][d] += __shfl_xor_sync(0xffffffffu, acc[qi][d], off);
        }
    }
    __syncthreads();
    if (lane == 0) {
        #pragma unroll
        for (int qi = 0; qi < 4; qi++) {
            float inv = 1.f / ssum[qi];
            #pragma unroll
            for (int d = 0; d < 8; d++) qs[(w4 + qi)*8 + d] = acc[qi][d] * inv;
        }
    }
    __syncthreads();
    {
        int b = bn >> 3, n = bn & 7;
        int yq = tid >> 3, d = tid & 7;
        g_attn[(b*SEQ + xi*32 + yq)*64 + n*8 + d] = qs[tid];
    }
}

// ================= output projection =================
__global__ __launch_bounds__(256) void proj_kernel(
    const float* __restrict__ w, const float* __restrict__ bias,
    float* __restrict__ out)
{
    __shared__ float at[32][64];
    __shared__ float ws[64][64];
    const int tid = threadIdx.x;
    const int p0  = blockIdx.x * 32;

    for (int i = tid; i < 32*64; i += 256) at[i >> 6][i & 63] = g_attn[p0*64 + i];
    for (int i = tid; i < 64*64; i += 256) ws[i >> 6][i & 63] = w[i];
    __syncthreads();

    const int o  = tid & 63;
    const int pg = tid >> 6;
    float acc[8];
    #pragma unroll
    for (int i = 0; i < 8; i++) acc[i] = 0.f;

    #pragma unroll
    for (int c = 0; c < 64; c++) {
        float wv = ws[c][o];
        #pragma unroll
        for (int i = 0; i < 8; i++)
            acc[i] = fmaf(at[pg + 4*i][c], wv, acc[i]);
    }
    float bb = bias[o];
    #pragma unroll
    for (int i = 0; i < 8; i++)
        out[(p0 + pg + 4*i)*256 + 192 + o] = acc[i] + bb;
}

// ================= launch =================
extern "C" void kernel_launch(void* const* d_in, const int* in_sizes, int n_in,
                              void* d_out, int out_size)
{
    const float* x       = (const float*)d_in[0];
    const float* conv_w  = (const float*)d_in[1];
    const float* conv_b  = (const float*)d_in[2];
    const float* qkv_w   = (const float*)d_in[3];
    const float* qkv_b   = (const float*)d_in[4];
    const float* attn_w  = (const float*)d_in[5];
    const float* attn_b  = (const float*)d_in[6];
    const float* relw    = (const float*)d_in[7];
    const float* relh    = (const float*)d_in[8];
    float* out = (float*)d_out;

    __nv_bfloat16 *bhi, *blo, *qbhi, *qblo;
    cudaGetSymbolAddress((void**)&bhi,  g_Bhi);
    cudaGetSymbolAddress((void**)&blo,  g_Blo);
    cudaGetSymbolAddress((void**)&qbhi, g_QBhi);
    cudaGetSymbolAddress((void**)&qblo, g_QBlo);

    const int ATTN_SMEM = 20736 * 4;
    cudaFuncSetAttribute(attn_kernel, cudaFuncAttributeMaxDynamicSharedMemorySize, ATTN_SMEM);
    cudaFuncSetAttribute(gemm_kernel<0>, cudaFuncAttributeMaxDynamicSharedMemorySize, GEMM_SMEM);
    cudaFuncSetAttribute(gemm_kernel<1>, cudaFuncAttributeMaxDynamicSharedMemorySize, GEMM_SMEM);

    bprep_kernel<<<(192*2304 + 192*256 + 255)/256, 256>>>(conv_w, qkv_w);
    gemm_kernel<1><<<128, 256, GEMM_SMEM>>>(x, qbhi, qblo, qkv_b, nullptr);
    gemm_kernel<0><<<128, 256, GEMM_SMEM>>>(x, bhi, blo, conv_b, out);
    attn_kernel<<<NB*NHEAD*HH, 256, ATTN_SMEM>>>(relw, relh);
    proj_kernel<<<NB*SEQ/32, 256>>>(attn_w, attn_b, out);
}